// round 8
// baseline (speedup 1.0000x reference)
#include <cuda_runtime.h>
#include <cstdint>

#define D      128
#define D4     32
#define KC     1024
#define MLVL   4
#define TM     128         // rows per block
#define TKC    64          // codes per chunk
#define NCH    (KC / TKC)  // 16
#define NTHR   128
#define RST    132         // padded row stride (floats)

__device__ float              g_e2[MLVL * KC];
__device__ unsigned long long g_lsum  = 0ULL;
__device__ unsigned int       g_count = 0u;

// smem layout (float offsets)
#define OFF_CS   (TM * RST)                 // 16896
#define OFF_E2   (OFF_CS + TKC * RST)       // 25344
#define OFF_R2S  (OFF_E2 + KC)              // 26368
#define OFF_IDX  (OFF_R2S + TM)             // 26496
#define SMEM_FLOATS (OFF_IDX + MLVL * TM)   // 27008
#define SMEM_BYTES  (SMEM_FLOATS * 4)       // 108032

#define LSCALE 17179869184.0                // 2^34

__device__ __forceinline__ void fma2(unsigned long long& acc,
                                     unsigned long long a,
                                     unsigned long long b) {
    asm("fma.rn.f32x2 %0, %1, %2, %3;" : "=l"(acc) : "l"(a), "l"(b), "l"(acc));
}
__device__ __forceinline__ void unpack2(unsigned long long v, float& lo, float& hi) {
    asm("mov.b64 {%0, %1}, %2;" : "=f"(lo), "=f"(hi) : "l"(v));
}
__device__ __forceinline__ void cp_async16(void* smem_dst, const void* gsrc) {
    unsigned saddr = (unsigned)__cvta_generic_to_shared(smem_dst);
    asm volatile("cp.async.ca.shared.global [%0], [%1], 16;" :: "r"(saddr), "l"(gsrc));
}

// ---- e2[k] = sum_d cb[k][d]^2, warp per code, coalesced ----
__global__ void e2_kernel(const float* __restrict__ cb) {
    int code = blockIdx.x * 4 + (threadIdx.x >> 5);
    int l = threadIdx.x & 31;
    const float4* row = (const float4*)(cb + (size_t)code * D);
    float4 v = row[l];
    float p = __fmaf_rn(v.x, v.x, 0.f);
    p = __fmaf_rn(v.y, v.y, p);
    p = __fmaf_rn(v.z, v.z, p);
    p = __fmaf_rn(v.w, v.w, p);
#pragma unroll
    for (int off = 16; off >= 1; off >>= 1)
        p = __fadd_rn(p, __shfl_xor_sync(0xffffffffu, p, off));
    if (l == 0) g_e2[code] = p;
}

__global__ __launch_bounds__(NTHR, 2)
void rvq_kernel(const float* __restrict__ x, const float* __restrict__ cb,
                float* __restrict__ y, float* __restrict__ loss_out,
                int nrows, long long nelems) {
    extern __shared__ float smem[];
    float* rs    = smem;                    // [TM][RST]
    float* cs    = smem + OFF_CS;           // [TKC][RST]
    float* e2all = smem + OFF_E2;           // [KC]
    float* r2s   = smem + OFF_R2S;          // [TM]
    int*   idxs  = (int*)(smem + OFF_IDX);  // [MLVL][TM]

    const int t    = threadIdx.x;
    const int w    = t >> 5;
    const int l    = t & 31;
    const int rowg = t >> 3;               // 0..15 -> rows rowg + 16*i (i=0..7)
    const int txc  = t & 7;                // 0..7  -> codes txc + 8*j (j=0..7)

    const int rowBase = blockIdx.x * TM;
    if (rowBase >= nrows) return;
    const float4* x4  = (const float4*)(x + (size_t)rowBase * D);
    const float4* cb4 = (const float4*)cb;

    double lsum = 0.0;

    // ---- initial residual load + r2 ----
#pragma unroll
    for (int i2 = 0; i2 < 32; i2++) {
        int row = w + 4 * i2;
        float4 v = x4[(size_t)row * D4 + l];
        *(float4*)&rs[row * RST + 4 * l] = v;
        float p = __fmaf_rn(v.x, v.x, 0.f);
        p = __fmaf_rn(v.y, v.y, p);
        p = __fmaf_rn(v.z, v.z, p);
        p = __fmaf_rn(v.w, v.w, p);
#pragma unroll
        for (int off = 16; off >= 1; off >>= 1)
            p = __fadd_rn(p, __shfl_xor_sync(0xffffffffu, p, off));
        if (l == 0) r2s[row] = p;
    }
    __syncthreads();

    const ulonglong2* rvp = (const ulonglong2*)&rs[rowg * RST];   // rows: +528*i
    const ulonglong2* cvp = (const ulonglong2*)&cs[txc * RST];    // codes: +264*j

    for (int lvl = 0; lvl < MLVL; lvl++) {
        const float4* cbl4 = cb4 + (size_t)lvl * KC * D4;

        // stage this level's e2 (fenced by the first chunk barrier)
        {
            const float4* e2src = (const float4*)(g_e2 + lvl * KC);
            float4 a = e2src[t];
            float4 b = e2src[t + NTHR];
            *(float4*)&e2all[4 * t] = a;
            *(float4*)&e2all[4 * (t + NTHR)] = b;
        }

        float r2r[8];
#pragma unroll
        for (int i = 0; i < 8; i++) r2r[i] = r2s[rowg + 16 * i];

        float bd[8]; int bi[8];
#pragma unroll
        for (int i = 0; i < 8; i++) { bd[i] = 3.4e38f; bi[i] = 0; }

        for (int c = 0; c < NCH; c++) {
            __syncthreads();   // previous chunk compute done -> cs free (also fences e2all)
            // ---- stage chunk via cp.async (coalesced, conflict-free STS) ----
            {
                const float4* src = cbl4 + (size_t)c * TKC * D4;
#pragma unroll
                for (int ii = 0; ii < 16; ii++) {
                    int e = t + NTHR * ii;           // 0..2047
                    int k = e >> 5, qq = e & 31;
                    cp_async16(&cs[k * RST + 4 * qq], src + e);
                }
                asm volatile("cp.async.commit_group;");
                asm volatile("cp.async.wait_group 0;");
            }
            __syncthreads();

            // ---- 8x8 register tile; cv prefetched one j ahead; no spills ----
            unsigned long long acc[8][8];
#pragma unroll
            for (int i = 0; i < 8; i++)
#pragma unroll
                for (int j = 0; j < 8; j++) acc[i][j] = 0ull;

            ulonglong2 cv = cvp[0];
            for (int q = 0; q < D4; q++) {
                ulonglong2 rv[8];
#pragma unroll
                for (int i = 0; i < 8; i++) rv[i] = rvp[528 * i + q];
                const int qn = (q + 1) & (D4 - 1);
#pragma unroll
                for (int j = 0; j < 8; j++) {
                    ulonglong2 cvN = (j < 7) ? cvp[264 * (j + 1) + q]
                                             : cvp[qn];
#pragma unroll
                    for (int i = 0; i < 8; i++) {
                        fma2(acc[i][j], rv[i].x, cv.x);
                        fma2(acc[i][j], rv[i].y, cv.y);
                    }
                    cv = cvN;
                }
            }

            // ---- distances + running argmin (ascending k, strict <) ----
#pragma unroll
            for (int j = 0; j < 8; j++) {
                int kk = txc + 8 * j;
                float e2k = e2all[c * TKC + kk];
                int kg = c * TKC + kk;
#pragma unroll
                for (int i = 0; i < 8; i++) {
                    float lo, hi;
                    unpack2(acc[i][j], lo, hi);
                    float dot = __fadd_rn(lo, hi);
                    float s = __fadd_rn(r2r[i], e2k);
                    float dv = __fmaf_rn(-2.0f, dot, s);
                    if (dv < bd[i]) { bd[i] = dv; bi[i] = kg; }
                }
            }
        }

        // ---- argmin across the 8 txc lanes (first-min via index tiebreak) ----
#pragma unroll
        for (int off = 1; off <= 4; off <<= 1)
#pragma unroll
            for (int i = 0; i < 8; i++) {
                float od = __shfl_xor_sync(0xffffffffu, bd[i], off);
                int   oi = __shfl_xor_sync(0xffffffffu, bi[i], off);
                if (od < bd[i] || (od == bd[i] && oi < bi[i])) { bd[i] = od; bi[i] = oi; }
            }
        if (txc == 0)
#pragma unroll
            for (int i = 0; i < 8; i++)
                idxs[lvl * TM + rowg + 16 * i] = bi[i];
        __syncthreads();

        // ---- residual update + r2 + loss partial ----
#pragma unroll
        for (int i2 = 0; i2 < 32; i2++) {
            int row = w + 4 * i2;
            int qi = idxs[lvl * TM + row];
            float4 qv = cbl4[(size_t)qi * D4 + l];
            float* rp = &rs[row * RST + 4 * l];
            float4 rv = *(float4*)rp;
            rv.x = __fsub_rn(rv.x, qv.x);
            rv.y = __fsub_rn(rv.y, qv.y);
            rv.z = __fsub_rn(rv.z, qv.z);
            rv.w = __fsub_rn(rv.w, qv.w);
            *(float4*)rp = rv;
            float p = __fmaf_rn(rv.x, rv.x, 0.f);
            p = __fmaf_rn(rv.y, rv.y, p);
            p = __fmaf_rn(rv.z, rv.z, p);
            p = __fmaf_rn(rv.w, rv.w, p);
            lsum += (double)p;               // (q - r_pre)^2 == r_post^2
#pragma unroll
            for (int off = 16; off >= 1; off >>= 1)
                p = __fadd_rn(p, __shfl_xor_sync(0xffffffffu, p, off));
            if (l == 0) r2s[row] = p;
        }
        __syncthreads();
    }

    // ---- y = x + (q_sum - x), reference rounding chain ----
    {
        float4* y4 = (float4*)(y + (size_t)rowBase * D);
#pragma unroll
        for (int i2 = 0; i2 < 32; i2++) {
            int row = w + 4 * i2;
            int a0 = idxs[0 * TM + row], a1 = idxs[1 * TM + row];
            int a2 = idxs[2 * TM + row], a3 = idxs[3 * TM + row];
            float4 q0 = cb4[((size_t)0 * KC + a0) * D4 + l];
            float4 q1 = cb4[((size_t)1 * KC + a1) * D4 + l];
            float4 q2 = cb4[((size_t)2 * KC + a2) * D4 + l];
            float4 q3 = cb4[((size_t)3 * KC + a3) * D4 + l];
            float4 xv = x4[(size_t)row * D4 + l];
            float4 o;
            o.x = __fadd_rn(xv.x, __fsub_rn(__fadd_rn(__fadd_rn(__fadd_rn(q0.x, q1.x), q2.x), q3.x), xv.x));
            o.y = __fadd_rn(xv.y, __fsub_rn(__fadd_rn(__fadd_rn(__fadd_rn(q0.y, q1.y), q2.y), q3.y), xv.y));
            o.z = __fadd_rn(xv.z, __fsub_rn(__fadd_rn(__fadd_rn(__fadd_rn(q0.z, q1.z), q2.z), q3.z), xv.z));
            o.w = __fadd_rn(xv.w, __fsub_rn(__fadd_rn(__fadd_rn(__fadd_rn(q0.w, q1.w), q2.w), q3.w), xv.w));
            y4[(size_t)row * D4 + l] = o;
        }
    }

    // ---- deterministic fixed-point loss reduction (int64, replay-safe) ----
    {
        long long lv = (long long)(lsum * LSCALE);
#pragma unroll
        for (int off = 16; off >= 1; off >>= 1)
            lv += __shfl_xor_sync(0xffffffffu, lv, off);
        if (l == 0) atomicAdd(&g_lsum, (unsigned long long)lv);
        __syncthreads();
        if (t == 0) {
            __threadfence();
            unsigned int prev = atomicAdd(&g_count, 1u);
            if (prev == gridDim.x - 1) {
                unsigned long long s = atomicExch(&g_lsum, 0ULL);
                loss_out[0] = (float)(1.25 * ((double)(long long)s / LSCALE)
                                           / (double)nelems);
                atomicExch(&g_count, 0u);
            }
        }
    }
}

extern "C" void kernel_launch(void* const* d_in, const int* in_sizes, int n_in,
                              void* d_out, int out_size) {
    const float* x  = (const float*)d_in[0];
    const float* cb = (const float*)d_in[1];
    float* y = (float*)d_out;

    const long long xelems = (long long)in_sizes[0];
    const int nrows   = (int)(xelems / D);
    const int nblocks = (nrows + TM - 1) / TM;
    float* loss_out = y + xelems;

    cudaFuncSetAttribute(rvq_kernel, cudaFuncAttributeMaxDynamicSharedMemorySize, SMEM_BYTES);

    e2_kernel<<<MLVL * KC / 4, 128>>>(cb);
    rvq_kernel<<<nblocks, NTHR, SMEM_BYTES>>>(x, cb, y, loss_out, nrows, xelems);
}

// round 9
// speedup vs baseline: 1.0787x; 1.0787x over previous
#include <cuda_runtime.h>
#include <cstdint>

#define D      128
#define D4     32
#define KC     1024
#define MLVL   4
#define TM     128         // rows per block
#define TKC    64          // codes per chunk
#define NCH    (KC / TKC)  // 16
#define NTHR   128
#define RST    132         // padded row stride (floats)

__device__ float              g_e2[MLVL * KC];
__device__ unsigned long long g_lsum  = 0ULL;
__device__ unsigned int       g_count = 0u;

// smem layout (float offsets)
#define OFF_CS   (TM * RST)                 // 16896
#define OFF_E2   (OFF_CS + TKC * RST)       // 25344
#define OFF_R2S  (OFF_E2 + KC)              // 26368
#define OFF_IDX  (OFF_R2S + TM)             // 26496
#define SMEM_FLOATS (OFF_IDX + MLVL * TM)   // 27008
#define SMEM_BYTES  (SMEM_FLOATS * 4)       // 108032

#define LSCALE 17179869184.0                // 2^34

__device__ __forceinline__ void fma2(unsigned long long& acc,
                                     unsigned long long a,
                                     unsigned long long b) {
    asm("fma.rn.f32x2 %0, %1, %2, %3;" : "=l"(acc) : "l"(a), "l"(b), "l"(acc));
}
__device__ __forceinline__ void unpack2(unsigned long long v, float& lo, float& hi) {
    asm("mov.b64 {%0, %1}, %2;" : "=f"(lo), "=f"(hi) : "l"(v));
}
__device__ __forceinline__ void cp_async16(void* smem_dst, const void* gsrc) {
    unsigned saddr = (unsigned)__cvta_generic_to_shared(smem_dst);
    asm volatile("cp.async.ca.shared.global [%0], [%1], 16;" :: "r"(saddr), "l"(gsrc));
}

// ---- e2[k] = sum_d cb[k][d]^2, warp per code, coalesced ----
__global__ void e2_kernel(const float* __restrict__ cb) {
    int code = blockIdx.x * 4 + (threadIdx.x >> 5);
    int l = threadIdx.x & 31;
    const float4* row = (const float4*)(cb + (size_t)code * D);
    float4 v = row[l];
    float p = __fmaf_rn(v.x, v.x, 0.f);
    p = __fmaf_rn(v.y, v.y, p);
    p = __fmaf_rn(v.z, v.z, p);
    p = __fmaf_rn(v.w, v.w, p);
#pragma unroll
    for (int off = 16; off >= 1; off >>= 1)
        p = __fadd_rn(p, __shfl_xor_sync(0xffffffffu, p, off));
    if (l == 0) g_e2[code] = p;
}

// one pipelined q-step: consumes RV, prefetches RVN (next q), cv carried in/out
#define QSTEP(QI, RV, RVN)                                              \
    {                                                                   \
        const int qn_ = ((QI) + 1) & (D4 - 1);                          \
        _Pragma("unroll")                                               \
        for (int j = 0; j < 8; j++) {                                   \
            ulonglong2 cvN_ = (j < 7) ? cvp[264 * (j + 1) + (QI)]       \
                                      : cvp[qn_];                       \
            (RVN)[j] = rvp[528 * j + qn_];                              \
            _Pragma("unroll")                                           \
            for (int i = 0; i < 8; i++) {                               \
                fma2(acc[i][j], (RV)[i].x, cv.x);                       \
                fma2(acc[i][j], (RV)[i].y, cv.y);                       \
            }                                                           \
            cv = cvN_;                                                  \
        }                                                               \
    }

__global__ __launch_bounds__(NTHR, 2)
void rvq_kernel(const float* __restrict__ x, const float* __restrict__ cb,
                float* __restrict__ y, float* __restrict__ loss_out,
                int nrows, long long nelems) {
    extern __shared__ float smem[];
    float* rs    = smem;                    // [TM][RST]
    float* cs    = smem + OFF_CS;           // [TKC][RST]
    float* e2all = smem + OFF_E2;           // [KC]
    float* r2s   = smem + OFF_R2S;          // [TM]
    int*   idxs  = (int*)(smem + OFF_IDX);  // [MLVL][TM]

    const int t    = threadIdx.x;
    const int w    = t >> 5;
    const int l    = t & 31;
    const int rowg = t >> 3;               // 0..15 -> rows rowg + 16*i (i=0..7)
    const int txc  = t & 7;                // 0..7  -> codes txc + 8*j (j=0..7)

    const int rowBase = blockIdx.x * TM;
    if (rowBase >= nrows) return;
    const float4* x4  = (const float4*)(x + (size_t)rowBase * D);
    const float4* cb4 = (const float4*)cb;

    double lsum = 0.0;

    // ---- kick off staging of chunk (lvl=0, c=0) right away ----
    {
#pragma unroll
        for (int ii = 0; ii < 16; ii++) {
            int e = t + NTHR * ii;
            int k = e >> 5, qq = e & 31;
            cp_async16(&cs[k * RST + 4 * qq], cb4 + e);
        }
        asm volatile("cp.async.commit_group;");
    }

    // ---- initial residual load + r2 (overlaps the copy above) ----
#pragma unroll
    for (int i2 = 0; i2 < 32; i2++) {
        int row = w + 4 * i2;
        float4 v = x4[(size_t)row * D4 + l];
        *(float4*)&rs[row * RST + 4 * l] = v;
        float p = __fmaf_rn(v.x, v.x, 0.f);
        p = __fmaf_rn(v.y, v.y, p);
        p = __fmaf_rn(v.z, v.z, p);
        p = __fmaf_rn(v.w, v.w, p);
#pragma unroll
        for (int off = 16; off >= 1; off >>= 1)
            p = __fadd_rn(p, __shfl_xor_sync(0xffffffffu, p, off));
        if (l == 0) r2s[row] = p;
    }

    const ulonglong2* rvp = (const ulonglong2*)&rs[rowg * RST];   // rows: +528*i
    const ulonglong2* cvp = (const ulonglong2*)&cs[txc * RST];    // codes: +264*j

    for (int lvl = 0; lvl < MLVL; lvl++) {
        const float4* cbl4 = cb4 + (size_t)lvl * KC * D4;

        // stage this level's e2 (read after the chunk-0 barrier below)
        {
            const float4* e2src = (const float4*)(g_e2 + lvl * KC);
            float4 a = e2src[t];
            float4 b = e2src[t + NTHR];
            *(float4*)&e2all[4 * t] = a;
            *(float4*)&e2all[4 * (t + NTHR)] = b;
        }

        float r2r[8];
#pragma unroll
        for (int i = 0; i < 8; i++) r2r[i] = r2s[rowg + 16 * i];

        float bd[8]; int bi[8];
#pragma unroll
        for (int i = 0; i < 8; i++) { bd[i] = 3.4e38f; bi[i] = 0; }

        for (int c = 0; c < NCH; c++) {
            // cs for this chunk was staged earlier; make it visible
            asm volatile("cp.async.wait_group 0;");
            __syncthreads();

            // ---- 8x8 tile, software-pipelined (cv 1-j ahead, rv ping-pong) ----
            unsigned long long acc[8][8];
#pragma unroll
            for (int i = 0; i < 8; i++)
#pragma unroll
                for (int j = 0; j < 8; j++) acc[i][j] = 0ull;

            ulonglong2 rvA[8], rvB[8];
#pragma unroll
            for (int i = 0; i < 8; i++) rvA[i] = rvp[528 * i];
            ulonglong2 cv = cvp[0];

            for (int qq = 0; qq < D4; qq += 2) {
                QSTEP(qq,     rvA, rvB)
                QSTEP(qq + 1, rvB, rvA)
            }

            __syncthreads();   // all warps done reading cs

            // ---- issue next chunk's copy NOW; it completes under the
            //      dist epilogue (and, at level end, under argmin+update) ----
            {
                const float4* nsrc = 0;
                if (c + 1 < NCH)         nsrc = cbl4 + (size_t)(c + 1) * TKC * D4;
                else if (lvl + 1 < MLVL) nsrc = cb4 + (size_t)(lvl + 1) * KC * D4;
                if (nsrc) {
#pragma unroll
                    for (int ii = 0; ii < 16; ii++) {
                        int e = t + NTHR * ii;
                        int k = e >> 5, qq2 = e & 31;
                        cp_async16(&cs[k * RST + 4 * qq2], nsrc + e);
                    }
                    asm volatile("cp.async.commit_group;");
                }
            }

            // ---- distances + running argmin (ascending k, strict <) ----
#pragma unroll
            for (int j = 0; j < 8; j++) {
                int kk = txc + 8 * j;
                float e2k = e2all[c * TKC + kk];
                int kg = c * TKC + kk;
#pragma unroll
                for (int i = 0; i < 8; i++) {
                    float lo, hi;
                    unpack2(acc[i][j], lo, hi);
                    float dot = __fadd_rn(lo, hi);
                    float s = __fadd_rn(r2r[i], e2k);
                    float dv = __fmaf_rn(-2.0f, dot, s);
                    if (dv < bd[i]) { bd[i] = dv; bi[i] = kg; }
                }
            }
        }

        // ---- argmin across the 8 txc lanes (first-min via index tiebreak) ----
#pragma unroll
        for (int off = 1; off <= 4; off <<= 1)
#pragma unroll
            for (int i = 0; i < 8; i++) {
                float od = __shfl_xor_sync(0xffffffffu, bd[i], off);
                int   oi = __shfl_xor_sync(0xffffffffu, bi[i], off);
                if (od < bd[i] || (od == bd[i] && oi < bi[i])) { bd[i] = od; bi[i] = oi; }
            }
        if (txc == 0)
#pragma unroll
            for (int i = 0; i < 8; i++)
                idxs[lvl * TM + rowg + 16 * i] = bi[i];
        __syncthreads();

        // ---- residual update + r2 + loss partial ----
#pragma unroll
        for (int i2 = 0; i2 < 32; i2++) {
            int row = w + 4 * i2;
            int qi = idxs[lvl * TM + row];
            float4 qv = cbl4[(size_t)qi * D4 + l];
            float* rp = &rs[row * RST + 4 * l];
            float4 rv = *(float4*)rp;
            rv.x = __fsub_rn(rv.x, qv.x);
            rv.y = __fsub_rn(rv.y, qv.y);
            rv.z = __fsub_rn(rv.z, qv.z);
            rv.w = __fsub_rn(rv.w, qv.w);
            *(float4*)rp = rv;
            float p = __fmaf_rn(rv.x, rv.x, 0.f);
            p = __fmaf_rn(rv.y, rv.y, p);
            p = __fmaf_rn(rv.z, rv.z, p);
            p = __fmaf_rn(rv.w, rv.w, p);
            lsum += (double)p;               // (q - r_pre)^2 == r_post^2
#pragma unroll
            for (int off = 16; off >= 1; off >>= 1)
                p = __fadd_rn(p, __shfl_xor_sync(0xffffffffu, p, off));
            if (l == 0) r2s[row] = p;
        }
        __syncthreads();
    }

    // ---- y = x + (q_sum - x), reference rounding chain ----
    {
        float4* y4 = (float4*)(y + (size_t)rowBase * D);
#pragma unroll
        for (int i2 = 0; i2 < 32; i2++) {
            int row = w + 4 * i2;
            int a0 = idxs[0 * TM + row], a1 = idxs[1 * TM + row];
            int a2 = idxs[2 * TM + row], a3 = idxs[3 * TM + row];
            float4 q0 = cb4[((size_t)0 * KC + a0) * D4 + l];
            float4 q1 = cb4[((size_t)1 * KC + a1) * D4 + l];
            float4 q2 = cb4[((size_t)2 * KC + a2) * D4 + l];
            float4 q3 = cb4[((size_t)3 * KC + a3) * D4 + l];
            float4 xv = x4[(size_t)row * D4 + l];
            float4 o;
            o.x = __fadd_rn(xv.x, __fsub_rn(__fadd_rn(__fadd_rn(__fadd_rn(q0.x, q1.x), q2.x), q3.x), xv.x));
            o.y = __fadd_rn(xv.y, __fsub_rn(__fadd_rn(__fadd_rn(__fadd_rn(q0.y, q1.y), q2.y), q3.y), xv.y));
            o.z = __fadd_rn(xv.z, __fsub_rn(__fadd_rn(__fadd_rn(__fadd_rn(q0.z, q1.z), q2.z), q3.z), xv.z));
            o.w = __fadd_rn(xv.w, __fsub_rn(__fadd_rn(__fadd_rn(__fadd_rn(q0.w, q1.w), q2.w), q3.w), xv.w));
            y4[(size_t)row * D4 + l] = o;
        }
    }

    // ---- deterministic fixed-point loss reduction (int64, replay-safe) ----
    {
        long long lv = (long long)(lsum * LSCALE);
#pragma unroll
        for (int off = 16; off >= 1; off >>= 1)
            lv += __shfl_xor_sync(0xffffffffu, lv, off);
        if (l == 0) atomicAdd(&g_lsum, (unsigned long long)lv);
        __syncthreads();
        if (t == 0) {
            __threadfence();
            unsigned int prev = atomicAdd(&g_count, 1u);
            if (prev == gridDim.x - 1) {
                unsigned long long s = atomicExch(&g_lsum, 0ULL);
                loss_out[0] = (float)(1.25 * ((double)(long long)s / LSCALE)
                                           / (double)nelems);
                atomicExch(&g_count, 0u);
            }
        }
    }
}

extern "C" void kernel_launch(void* const* d_in, const int* in_sizes, int n_in,
                              void* d_out, int out_size) {
    const float* x  = (const float*)d_in[0];
    const float* cb = (const float*)d_in[1];
    float* y = (float*)d_out;

    const long long xelems = (long long)in_sizes[0];
    const int nrows   = (int)(xelems / D);
    const int nblocks = (nrows + TM - 1) / TM;
    float* loss_out = y + xelems;

    cudaFuncSetAttribute(rvq_kernel, cudaFuncAttributeMaxDynamicSharedMemorySize, SMEM_BYTES);

    e2_kernel<<<MLVL * KC / 4, 128>>>(cb);
    rvq_kernel<<<nblocks, NTHR, SMEM_BYTES>>>(x, cb, y, loss_out, nrows, xelems);
}